// round 1
// baseline (speedup 1.0000x reference)
#include <cuda_runtime.h>
#include <math.h>
#include <stdint.h>

#define N_NODES 500000
#define N_SEG   10000
#define DIM     256
#define NGATE   1024      // 4*DIM
#define QSTAR   512       // 2*DIM
#define NITER   6

// ---------------- scratch (device globals; no allocation allowed) ----------
__device__ float g_gates[(size_t)N_SEG * NGATE];          // 40 MB
__device__ float g_h[3 * N_SEG * DIM];                    // 30 MB
__device__ float g_c[3 * N_SEG * DIM];                    // 30 MB
__device__ float g_e[N_NODES];                            // 2 MB
__device__ int   g_start[N_SEG + 1];

// ---------------- utility: zero fill ----------------------------------------
__global__ void zero_kernel(float* __restrict__ p, size_t n) {
    size_t i = (size_t)blockIdx.x * blockDim.x + threadIdx.x;
    size_t stride = (size_t)gridDim.x * blockDim.x;
    for (; i < n; i += stride) p[i] = 0.0f;
}

// ---------------- segment starts via binary search ---------------------------
__global__ void seg_start_kernel(const int* __restrict__ seg) {
    int s = blockIdx.x * blockDim.x + threadIdx.x;
    if (s > N_SEG) return;
    int lo = 0, hi = N_NODES;
    while (lo < hi) {
        int mid = (lo + hi) >> 1;
        if (seg[mid] < s) lo = mid + 1; else hi = mid;
    }
    g_start[s] = lo;
}

// ---------------- dual-operand SGEMM: C = A1*W1^T + A2*W2^T -----------------
// A1: [M,K1], W1: [N,K1], A2: [M,K2], W2: [N,K2], C: [M,N]
// 128x128 block tile, BK=8, 256 threads, 8x8 per thread (strided mapping).
#define BM 128
#define BN 128
#define BK 8
#define TM 8
#define TN 8

__global__ void gemm_dual(const float* __restrict__ A1, const float* __restrict__ W1, int K1,
                          const float* __restrict__ A2, const float* __restrict__ W2, int K2,
                          float* __restrict__ C, int M, int N) {
    __shared__ float As[BK][BM];
    __shared__ float Bs[BK][BN];

    const int bm = blockIdx.x * BM;
    const int bn = blockIdx.y * BN;
    const int tid = threadIdx.x;
    const int tx = tid & 15;   // N direction (16)
    const int ty = tid >> 4;   // M direction (16)

    // loader mapping: 128 rows x 8 k, one float4 per thread
    const int l_row = tid >> 1;          // 0..127
    const int l_col = (tid & 1) * 4;     // 0 or 4

    float acc[TM][TN];
#pragma unroll
    for (int i = 0; i < TM; i++)
#pragma unroll
        for (int j = 0; j < TN; j++) acc[i][j] = 0.0f;

#pragma unroll 1
    for (int pass = 0; pass < 2; pass++) {
        const float* A = pass ? A2 : A1;
        const float* W = pass ? W2 : W1;
        const int K = pass ? K2 : K1;

        for (int k0 = 0; k0 < K; k0 += BK) {
            // load A tile (guard M)
            int gm = bm + l_row;
            float4 av = make_float4(0.f, 0.f, 0.f, 0.f);
            if (gm < M) av = *(const float4*)(A + (size_t)gm * K + k0 + l_col);
            As[l_col + 0][l_row] = av.x;
            As[l_col + 1][l_row] = av.y;
            As[l_col + 2][l_row] = av.z;
            As[l_col + 3][l_row] = av.w;
            // load W tile (N=1024 multiple of 128, no guard needed)
            int gn = bn + l_row;
            float4 bv = *(const float4*)(W + (size_t)gn * K + k0 + l_col);
            Bs[l_col + 0][l_row] = bv.x;
            Bs[l_col + 1][l_row] = bv.y;
            Bs[l_col + 2][l_row] = bv.z;
            Bs[l_col + 3][l_row] = bv.w;
            __syncthreads();

#pragma unroll
            for (int k = 0; k < BK; k++) {
                float a[TM], b[TN];
#pragma unroll
                for (int i = 0; i < TM; i++) a[i] = As[k][ty + 16 * i];
#pragma unroll
                for (int j = 0; j < TN; j++) b[j] = Bs[k][tx + 16 * j];
#pragma unroll
                for (int i = 0; i < TM; i++)
#pragma unroll
                    for (int j = 0; j < TN; j++) acc[i][j] = fmaf(a[i], b[j], acc[i][j]);
            }
            __syncthreads();
        }
    }

#pragma unroll
    for (int i = 0; i < TM; i++) {
        int row = bm + ty + 16 * i;
        if (row >= M) continue;
        float* crow = C + (size_t)row * N + bn;
#pragma unroll
        for (int j = 0; j < TN; j++) crow[tx + 16 * j] = acc[i][j];
    }
}

// ---------------- LSTM gate activation ---------------------------------------
__global__ void lstm_act(const float* __restrict__ gates,
                         const float* __restrict__ b_ih, const float* __restrict__ b_hh,
                         float* __restrict__ h, float* __restrict__ c) {
    int idx = blockIdx.x * blockDim.x + threadIdx.x;   // over N_SEG*DIM
    if (idx >= N_SEG * DIM) return;
    int b = idx >> 8;          // /256
    int u = idx & 255;
    const float* g = gates + (size_t)b * NGATE;
    float gi = g[u]       + b_ih[u]       + b_hh[u];
    float gf = g[u + 256] + b_ih[u + 256] + b_hh[u + 256];
    float gg = g[u + 512] + b_ih[u + 512] + b_hh[u + 512];
    float go = g[u + 768] + b_ih[u + 768] + b_hh[u + 768];
    float ig = 1.0f / (1.0f + expf(-gi));
    float fg = 1.0f / (1.0f + expf(-gf));
    float gt = tanhf(gg);
    float og = 1.0f / (1.0f + expf(-go));
    float cn = fg * c[idx] + ig * gt;
    c[idx] = cn;
    h[idx] = og * tanhf(cn);
}

// ---------------- attention logits: e[n] = dot(feats[n], q[seg[n]]) ----------
__global__ void e_kernel(const float* __restrict__ feats, const float* __restrict__ q,
                         const int* __restrict__ seg) {
    int warp = (blockIdx.x * blockDim.x + threadIdx.x) >> 5;
    int lane = threadIdx.x & 31;
    if (warp >= N_NODES) return;
    int s = seg[warp];
    const float4* f = (const float4*)(feats + (size_t)warp * DIM);
    const float4* qq = (const float4*)(q + (size_t)s * DIM);
    float sum = 0.0f;
#pragma unroll
    for (int r = 0; r < 2; r++) {
        float4 a = f[lane + 32 * r];
        float4 b = qq[lane + 32 * r];
        sum += a.x * b.x + a.y * b.y + a.z * b.z + a.w * b.w;
    }
#pragma unroll
    for (int o = 16; o > 0; o >>= 1) sum += __shfl_down_sync(0xffffffffu, sum, o);
    if (lane == 0) g_e[warp] = sum;
}

// ---------------- segment softmax + weighted sum + q_star write --------------
// one block (256 threads) per segment. Writes out[s] = [q[s], r[s]].
__global__ void softmax_r_kernel(const float* __restrict__ feats, const float* __restrict__ q,
                                 float* __restrict__ out) {
    int s = blockIdx.x;
    int lo = g_start[s], hi = g_start[s + 1];
    int t = threadIdx.x;
    __shared__ float red[256];

    // pass 1: max
    float m = -INFINITY;
    for (int n = lo + t; n < hi; n += 256) m = fmaxf(m, g_e[n]);
    red[t] = m; __syncthreads();
#pragma unroll
    for (int o = 128; o > 0; o >>= 1) {
        if (t < o) red[t] = fmaxf(red[t], red[t + o]);
        __syncthreads();
    }
    m = red[0]; __syncthreads();

    // pass 2: exp & sum (write exp back into g_e)
    float sum = 0.0f;
    for (int n = lo + t; n < hi; n += 256) {
        float ex = expf(g_e[n] - m);
        g_e[n] = ex;
        sum += ex;
    }
    red[t] = sum; __syncthreads();
#pragma unroll
    for (int o = 128; o > 0; o >>= 1) {
        if (t < o) red[t] += red[t + o];
        __syncthreads();
    }
    float inv = (hi > lo) ? 1.0f / red[0] : 0.0f;
    __syncthreads();

    // pass 3: r[t] = sum_n alpha_n * feats[n][t]
    float r = 0.0f;
    for (int n = lo; n < hi; n++) {
        float w = g_e[n] * inv;                      // broadcast load
        r = fmaf(w, feats[(size_t)n * DIM + t], r);  // coalesced load
    }
    out[(size_t)s * QSTAR + t]       = q[(size_t)s * DIM + t];
    out[(size_t)s * QSTAR + 256 + t] = r;
}

// ---------------- host orchestration -----------------------------------------
extern "C" void kernel_launch(void* const* d_in, const int* in_sizes, int n_in,
                              void* d_out, int out_size) {
    const float* feats = (const float*)d_in[0];
    const int* seg = (const int*)d_in[1];
    const float* w_ih[3] = {(const float*)d_in[2], (const float*)d_in[6], (const float*)d_in[10]};
    const float* w_hh[3] = {(const float*)d_in[3], (const float*)d_in[7], (const float*)d_in[11]};
    const float* b_ih[3] = {(const float*)d_in[4], (const float*)d_in[8], (const float*)d_in[12]};
    const float* b_hh[3] = {(const float*)d_in[5], (const float*)d_in[9], (const float*)d_in[13]};
    float* out = (float*)d_out;

    float *gates, *h, *c;
    cudaGetSymbolAddress((void**)&gates, g_gates);
    cudaGetSymbolAddress((void**)&h, g_h);
    cudaGetSymbolAddress((void**)&c, g_c);

    // init state: q_star = 0, h = 0, c = 0
    zero_kernel<<<592, 256>>>(out, (size_t)N_SEG * QSTAR);
    zero_kernel<<<592, 256>>>(h, (size_t)3 * N_SEG * DIM);
    zero_kernel<<<592, 256>>>(c, (size_t)3 * N_SEG * DIM);
    seg_start_kernel<<<(N_SEG + 256) / 256, 256>>>(seg);

    dim3 ggrid((N_SEG + BM - 1) / BM, NGATE / BN);

    for (int it = 0; it < NITER; it++) {
        for (int l = 0; l < 3; l++) {
            const float* x = (l == 0) ? out : (h + (size_t)(l - 1) * N_SEG * DIM);
            int Kx = (l == 0) ? QSTAR : DIM;
            float* hl = h + (size_t)l * N_SEG * DIM;
            float* cl = c + (size_t)l * N_SEG * DIM;
            gemm_dual<<<ggrid, 256>>>(x, w_ih[l], Kx, hl, w_hh[l], DIM, gates, N_SEG, NGATE);
            lstm_act<<<(N_SEG * DIM + 255) / 256, 256>>>(gates, b_ih[l], b_hh[l], hl, cl);
        }
        const float* qtop = h + (size_t)2 * N_SEG * DIM;
        e_kernel<<<(N_NODES + 7) / 8, 256>>>(feats, qtop, seg);
        softmax_r_kernel<<<N_SEG, 256>>>(feats, qtop, out);
    }
}

// round 2
// speedup vs baseline: 1.1601x; 1.1601x over previous
#include <cuda_runtime.h>
#include <math.h>
#include <stdint.h>

#define N_NODES 500000
#define N_SEG   10000
#define DIM     256
#define NGATE   1024      // 4*DIM
#define QSTAR   512       // 2*DIM
#define NITER   6

typedef unsigned long long u64;

// ---------------- scratch (device globals; no allocation allowed) ----------
__device__ float g_gates[(size_t)N_SEG * NGATE];          // 40 MB
__device__ float g_h[3 * N_SEG * DIM];                    // 30 MB
__device__ float g_c[3 * N_SEG * DIM];                    // 30 MB
__device__ int   g_start[N_SEG + 1];

// ---------------- packed f32x2 helpers ---------------------------------------
__device__ __forceinline__ u64 splat2(float x) {
    u64 r; asm("mov.b64 %0, {%1, %1};" : "=l"(r) : "f"(x)); return r;
}
__device__ __forceinline__ void fma2(u64& d, u64 a, u64 b) {
    asm("fma.rn.f32x2 %0, %1, %2, %3;" : "=l"(d) : "l"(a), "l"(b), "l"(d));
}
__device__ __forceinline__ float2 unpack2(u64 v) {
    float lo, hi; asm("mov.b64 {%0, %1}, %2;" : "=f"(lo), "=f"(hi) : "l"(v));
    return make_float2(lo, hi);
}

// ---------------- utility: zero fill ----------------------------------------
__global__ void zero_kernel(float* __restrict__ p, size_t n) {
    size_t i = (size_t)blockIdx.x * blockDim.x + threadIdx.x;
    size_t stride = (size_t)gridDim.x * blockDim.x;
    for (; i < n; i += stride) p[i] = 0.0f;
}

// ---------------- segment starts via binary search ---------------------------
__global__ void seg_start_kernel(const int* __restrict__ seg) {
    int s = blockIdx.x * blockDim.x + threadIdx.x;
    if (s > N_SEG) return;
    int lo = 0, hi = N_NODES;
    while (lo < hi) {
        int mid = (lo + hi) >> 1;
        if (seg[mid] < s) lo = mid + 1; else hi = mid;
    }
    g_start[s] = lo;
}

// ---------------- dual-operand SGEMM with packed f32x2 FMA -------------------
// C = A1*W1^T + A2*W2^T.  A: [M,K], W: [N,K], C: [M,N].
// 128x128 tile, BK=8, 256 threads. Thread tile: 8 rows x 4 column-pairs.
// A is stored in smem pre-splatted (each value duplicated into a 64-bit pair)
// so the inner loop is pure LDS.64 + fma.rn.f32x2.
#define BM 128
#define BN 128
#define BK 8

__global__ __launch_bounds__(256, 2)
void gemm_dual2(const float* __restrict__ A1, const float* __restrict__ W1, int K1,
                const float* __restrict__ A2, const float* __restrict__ W2, int K2,
                float* __restrict__ C, int M, int N) {
    __shared__ u64   As2[BK][BM];     // splatted A values, 8 KB
    __shared__ float Bs[BK][BN];      // 4 KB

    const int bm = blockIdx.x * BM;
    const int bn = blockIdx.y * BN;
    const int tid = threadIdx.x;
    const int tx = tid & 15;          // column-pair group (16)
    const int ty = tid >> 4;          // row group (16)

    const int l_row = tid >> 1;       // 0..127
    const int l_col = (tid & 1) * 4;  // 0 or 4

    u64 acc[8][4];
#pragma unroll
    for (int i = 0; i < 8; i++)
#pragma unroll
        for (int j = 0; j < 4; j++) acc[i][j] = 0ull;

#pragma unroll 1
    for (int pass = 0; pass < 2; pass++) {
        const float* A = pass ? A2 : A1;
        const float* W = pass ? W2 : W1;
        const int K = pass ? K2 : K1;

        for (int k0 = 0; k0 < K; k0 += BK) {
            int gm = bm + l_row;
            float4 av = make_float4(0.f, 0.f, 0.f, 0.f);
            if (gm < M) av = *(const float4*)(A + (size_t)gm * K + k0 + l_col);
            As2[l_col + 0][l_row] = splat2(av.x);
            As2[l_col + 1][l_row] = splat2(av.y);
            As2[l_col + 2][l_row] = splat2(av.z);
            As2[l_col + 3][l_row] = splat2(av.w);

            int gn = bn + l_row;
            float4 bv = *(const float4*)(W + (size_t)gn * K + k0 + l_col);
            Bs[l_col + 0][l_row] = bv.x;
            Bs[l_col + 1][l_row] = bv.y;
            Bs[l_col + 2][l_row] = bv.z;
            Bs[l_col + 3][l_row] = bv.w;
            __syncthreads();

#pragma unroll
            for (int k = 0; k < BK; k++) {
                u64 a2r[8], b2r[4];
#pragma unroll
                for (int i = 0; i < 8; i++) a2r[i] = As2[k][ty + 16 * i];
#pragma unroll
                for (int j = 0; j < 4; j++) b2r[j] = *(const u64*)&Bs[k][tx * 2 + 32 * j];
#pragma unroll
                for (int i = 0; i < 8; i++)
#pragma unroll
                    for (int j = 0; j < 4; j++) fma2(acc[i][j], a2r[i], b2r[j]);
            }
            __syncthreads();
        }
    }

#pragma unroll
    for (int i = 0; i < 8; i++) {
        int row = bm + ty + 16 * i;
        if (row >= M) continue;
        float* crow = C + (size_t)row * N + bn;
#pragma unroll
        for (int j = 0; j < 4; j++) {
            float2 v = unpack2(acc[i][j]);
            *(float2*)&crow[tx * 2 + 32 * j] = v;
        }
    }
}

// ---------------- LSTM gate activation ---------------------------------------
__global__ void lstm_act(const float* __restrict__ gates,
                         const float* __restrict__ b_ih, const float* __restrict__ b_hh,
                         float* __restrict__ h, float* __restrict__ c) {
    int idx = blockIdx.x * blockDim.x + threadIdx.x;   // over N_SEG*DIM
    if (idx >= N_SEG * DIM) return;
    int b = idx >> 8;
    int u = idx & 255;
    const float* g = gates + (size_t)b * NGATE;
    float gi = g[u]       + b_ih[u]       + b_hh[u];
    float gf = g[u + 256] + b_ih[u + 256] + b_hh[u + 256];
    float gg = g[u + 512] + b_ih[u + 512] + b_hh[u + 512];
    float go = g[u + 768] + b_ih[u + 768] + b_hh[u + 768];
    float ig = 1.0f / (1.0f + expf(-gi));
    float fg = 1.0f / (1.0f + expf(-gf));
    float gt = tanhf(gg);
    float og = 1.0f / (1.0f + expf(-go));
    float cn = fg * c[idx] + ig * gt;
    c[idx] = cn;
    h[idx] = og * tanhf(cn);
}

// ---------------- fused attention: online softmax over each segment ----------
// One block (8 warps) per segment. Each warp processes nodes lo+w, lo+w+8, ...
// maintaining an online-softmax state (m, s, r[256-dim, 8 floats/lane]).
// feats is read ONCE per iteration. Partials merged across warps in smem.
__global__ void attn_kernel(const float* __restrict__ feats,
                            const float* __restrict__ q,
                            float* __restrict__ out) {
    const int s = blockIdx.x;
    const int lo = g_start[s], hi = g_start[s + 1];
    const int w = threadIdx.x >> 5;
    const int lane = threadIdx.x & 31;

    __shared__ float sm_m[8];
    __shared__ float sm_s[8];
    __shared__ float sm_r[8][256];

    const float4* qv = (const float4*)(q + (size_t)s * DIM);
    float4 q0 = qv[lane];
    float4 q1 = qv[lane + 32];

    float m = -INFINITY, ssum = 0.0f;
    float4 r0 = make_float4(0.f, 0.f, 0.f, 0.f);
    float4 r1 = make_float4(0.f, 0.f, 0.f, 0.f);

    for (int n = lo + w; n < hi; n += 8) {
        const float4* f = (const float4*)(feats + (size_t)n * DIM);
        float4 f0 = f[lane];
        float4 f1 = f[lane + 32];
        float d = f0.x * q0.x + f0.y * q0.y + f0.z * q0.z + f0.w * q0.w
                + f1.x * q1.x + f1.y * q1.y + f1.z * q1.z + f1.w * q1.w;
#pragma unroll
        for (int o = 16; o > 0; o >>= 1) d += __shfl_xor_sync(0xffffffffu, d, o);

        float mn = fmaxf(m, d);
        float sc = __expf(m - mn);     // first iter: exp(-inf)=0, state is 0 anyway
        float p  = __expf(d - mn);
        ssum = ssum * sc + p;
        r0.x = r0.x * sc + p * f0.x;  r0.y = r0.y * sc + p * f0.y;
        r0.z = r0.z * sc + p * f0.z;  r0.w = r0.w * sc + p * f0.w;
        r1.x = r1.x * sc + p * f1.x;  r1.y = r1.y * sc + p * f1.y;
        r1.z = r1.z * sc + p * f1.z;  r1.w = r1.w * sc + p * f1.w;
        m = mn;
    }

    if (lane == 0) { sm_m[w] = m; sm_s[w] = ssum; }
    *(float4*)&sm_r[w][4 * lane]       = r0;
    *(float4*)&sm_r[w][128 + 4 * lane] = r1;
    __syncthreads();

    // merge: thread t owns output dim t
    const int t = threadIdx.x;
    float M = -INFINITY;
#pragma unroll
    for (int k = 0; k < 8; k++)
        if (sm_s[k] > 0.0f) M = fmaxf(M, sm_m[k]);
    float S = 0.0f, R = 0.0f;
#pragma unroll
    for (int k = 0; k < 8; k++) {
        if (sm_s[k] > 0.0f) {
            float sc = __expf(sm_m[k] - M);
            S += sm_s[k] * sc;
            R += sm_r[k][t] * sc;
        }
    }
    float rv = (S > 0.0f) ? R / S : 0.0f;
    out[(size_t)s * QSTAR + t]       = q[(size_t)s * DIM + t];
    out[(size_t)s * QSTAR + DIM + t] = rv;
}

// ---------------- host orchestration -----------------------------------------
extern "C" void kernel_launch(void* const* d_in, const int* in_sizes, int n_in,
                              void* d_out, int out_size) {
    const float* feats = (const float*)d_in[0];
    const int* seg = (const int*)d_in[1];
    const float* w_ih[3] = {(const float*)d_in[2], (const float*)d_in[6], (const float*)d_in[10]};
    const float* w_hh[3] = {(const float*)d_in[3], (const float*)d_in[7], (const float*)d_in[11]};
    const float* b_ih[3] = {(const float*)d_in[4], (const float*)d_in[8], (const float*)d_in[12]};
    const float* b_hh[3] = {(const float*)d_in[5], (const float*)d_in[9], (const float*)d_in[13]};
    float* out = (float*)d_out;

    float *gates, *h, *c;
    cudaGetSymbolAddress((void**)&gates, g_gates);
    cudaGetSymbolAddress((void**)&h, g_h);
    cudaGetSymbolAddress((void**)&c, g_c);

    // init state: q_star = 0, h = 0, c = 0
    zero_kernel<<<592, 256>>>(out, (size_t)N_SEG * QSTAR);
    zero_kernel<<<592, 256>>>(h, (size_t)3 * N_SEG * DIM);
    zero_kernel<<<592, 256>>>(c, (size_t)3 * N_SEG * DIM);
    seg_start_kernel<<<(N_SEG + 256) / 256, 256>>>(seg);

    dim3 ggrid((N_SEG + BM - 1) / BM, NGATE / BN);

    for (int it = 0; it < NITER; it++) {
        for (int l = 0; l < 3; l++) {
            const float* x = (l == 0) ? out : (h + (size_t)(l - 1) * N_SEG * DIM);
            int Kx = (l == 0) ? QSTAR : DIM;
            float* hl = h + (size_t)l * N_SEG * DIM;
            float* cl = c + (size_t)l * N_SEG * DIM;
            gemm_dual2<<<ggrid, 256>>>(x, w_ih[l], Kx, hl, w_hh[l], DIM, gates, N_SEG, NGATE);
            lstm_act<<<(N_SEG * DIM + 255) / 256, 256>>>(gates, b_ih[l], b_hh[l], hl, cl);
        }
        const float* qtop = h + (size_t)2 * N_SEG * DIM;
        attn_kernel<<<N_SEG, 256>>>(feats, qtop, out);
    }
}

// round 3
// speedup vs baseline: 1.2697x; 1.0945x over previous
#include <cuda_runtime.h>
#include <math.h>
#include <stdint.h>

#define N_NODES 500000
#define N_SEG   10000
#define DIM     256
#define NGATE   1024
#define QSTAR   512
#define NITER   6
#define SD      (N_SEG * DIM)

typedef unsigned long long u64;

// ---------------- scratch (device globals) -----------------------------------
__device__ float g_h[2 * 3 * SD];                 // ping-pong h, 60 MB
__device__ float g_c[3 * SD];                     // 30 MB
__device__ float g_wp_ih[3 * NGATE * 512];        // permuted w_ih (max K=512), 6 MB
__device__ float g_wp_hh[3 * NGATE * DIM];        // permuted w_hh, 3 MB
__device__ float g_bp[3 * NGATE];                 // combined permuted bias
__device__ int   g_start[N_SEG + 1];

// ---------------- packed f32x2 helpers ---------------------------------------
__device__ __forceinline__ u64 splat2(float x) {
    u64 r; asm("mov.b64 %0, {%1, %1};" : "=l"(r) : "f"(x)); return r;
}
__device__ __forceinline__ void fma2(u64& d, u64 a, u64 b) {
    asm("fma.rn.f32x2 %0, %1, %2, %3;" : "=l"(d) : "l"(a), "l"(b), "l"(d));
}
__device__ __forceinline__ float2 unpack2(u64 v) {
    float lo, hi; asm("mov.b64 {%0, %1}, %2;" : "=f"(lo), "=f"(hi) : "l"(v));
    return make_float2(lo, hi);
}
__device__ __forceinline__ float sigf(float x) { return 1.0f / (1.0f + __expf(-x)); }
__device__ __forceinline__ float tanhfast(float x) { return 2.0f / (1.0f + __expf(-2.0f * x)) - 1.0f; }

// ---------------- prep: permute weights to gate-interleaved layout -----------
// dst row r = u*4+g  <-  src row g*256+u ; bias combined.
struct PermArgs {
    const float* w_ih[3]; const float* w_hh[3];
    const float* b_ih[3]; const float* b_hh[3];
    int K1[3];
};
__global__ void prep_kernel(PermArgs pa) {
    int l = blockIdx.y;
    int K1 = pa.K1[l];
    float* wih_dst = g_wp_ih + (size_t)l * NGATE * 512;
    float* whh_dst = g_wp_hh + (size_t)l * NGATE * DIM;
    float* b_dst   = g_bp + l * NGATE;
    int n_ih = NGATE * K1, n_hh = NGATE * DIM;
    int total = n_ih + n_hh + NGATE;
    for (int i = blockIdx.x * blockDim.x + threadIdx.x; i < total; i += gridDim.x * blockDim.x) {
        if (i < n_ih) {
            int row = i / K1, k = i - row * K1;
            int u = row >> 2, g = row & 3;
            wih_dst[i] = pa.w_ih[l][(size_t)(g * 256 + u) * K1 + k];
        } else if (i < n_ih + n_hh) {
            int j = i - n_ih;
            int row = j / DIM, k = j - row * DIM;
            int u = row >> 2, g = row & 3;
            whh_dst[j] = pa.w_hh[l][(size_t)(g * 256 + u) * DIM + k];
        } else {
            int row = i - n_ih - n_hh;
            int u = row >> 2, g = row & 3;
            b_dst[row] = pa.b_ih[l][g * 256 + u] + pa.b_hh[l][g * 256 + u];
        }
    }
}

// ---------------- init: zero state + segment starts --------------------------
__global__ void init_kernel(const int* __restrict__ seg, float* __restrict__ out) {
    size_t gid = (size_t)blockIdx.x * blockDim.x + threadIdx.x;
    size_t stride = (size_t)gridDim.x * blockDim.x;
    for (size_t i = gid; i < (size_t)N_SEG * QSTAR; i += stride) out[i] = 0.0f;
    for (size_t i = gid; i < (size_t)3 * SD; i += stride) { g_h[i] = 0.0f; g_c[i] = 0.0f; }
    if (gid <= N_SEG) {
        int s = (int)gid;
        int lo = 0, hi = N_NODES;
        while (lo < hi) { int mid = (lo + hi) >> 1; if (seg[mid] < s) lo = mid + 1; else hi = mid; }
        g_start[s] = lo;
    }
}

// ---------------- fused dual-GEMM + LSTM cell ---------------------------------
// gates(pre-act) = A1*W1'^T + A2*W2'^T (+bias), W' gate-interleaved.
// Epilogue computes c,h in place. 128x128x16 tiles, double-buffered,
// f32x2 packed FMA, LDS.128 fragment loads.
#define BM 128
#define BN 128
#define BK 16

__global__ __launch_bounds__(256, 2)
void gemm_lstm(const float* __restrict__ A1, int K1, const float* __restrict__ W1,
               const float* __restrict__ A2, const float* __restrict__ W2,
               const float* __restrict__ bias,
               float* __restrict__ c, float* __restrict__ hout, int M) {
    __shared__ __align__(16) u64   As2[2][BK][BM];   // splatted A, 32 KB
    __shared__ __align__(16) float Bs[2][BK][BN];    // 16 KB

    const int bm = blockIdx.x * BM;
    const int bn = blockIdx.y * BN;
    const int tid = threadIdx.x;
    const int tx = tid & 15;           // column group
    const int ty = tid >> 4;           // row group (8 contiguous rows each)
    const int l_row = tid >> 1;        // loader row 0..127
    const int l_k   = (tid & 1) * 8;   // loader k offset 0 or 8

    const int T1 = K1 / BK;            // tiles in pass 1
    const int T  = T1 + DIM / BK;      // + pass 2 (K2=256)

    u64 acc[8][4];
#pragma unroll
    for (int i = 0; i < 8; i++)
#pragma unroll
        for (int j = 0; j < 4; j++) acc[i][j] = 0ull;

    float4 ra0, ra1, rb0, rb1;

    // --- tile fetch into registers ---
    auto fetch = [&](int t) {
        const float* A; const float* W; int K, k0;
        if (t < T1) { A = A1; W = W1; K = K1; k0 = t * BK; }
        else        { A = A2; W = W2; K = DIM; k0 = (t - T1) * BK; }
        int gm = bm + l_row;
        if (gm < M) {
            const float* ap = A + (size_t)gm * K + k0 + l_k;
            ra0 = *(const float4*)ap; ra1 = *(const float4*)(ap + 4);
        } else {
            ra0 = make_float4(0.f,0.f,0.f,0.f); ra1 = ra0;
        }
        const float* wp = W + (size_t)(bn + l_row) * K + k0 + l_k;
        rb0 = *(const float4*)wp; rb1 = *(const float4*)(wp + 4);
    };
    auto store_stage = [&](int st) {
        As2[st][l_k + 0][l_row] = splat2(ra0.x);
        As2[st][l_k + 1][l_row] = splat2(ra0.y);
        As2[st][l_k + 2][l_row] = splat2(ra0.z);
        As2[st][l_k + 3][l_row] = splat2(ra0.w);
        As2[st][l_k + 4][l_row] = splat2(ra1.x);
        As2[st][l_k + 5][l_row] = splat2(ra1.y);
        As2[st][l_k + 6][l_row] = splat2(ra1.z);
        As2[st][l_k + 7][l_row] = splat2(ra1.w);
        Bs[st][l_k + 0][l_row] = rb0.x;
        Bs[st][l_k + 1][l_row] = rb0.y;
        Bs[st][l_k + 2][l_row] = rb0.z;
        Bs[st][l_k + 3][l_row] = rb0.w;
        Bs[st][l_k + 4][l_row] = rb1.x;
        Bs[st][l_k + 5][l_row] = rb1.y;
        Bs[st][l_k + 6][l_row] = rb1.z;
        Bs[st][l_k + 7][l_row] = rb1.w;
    };

    fetch(0);
    store_stage(0);
    __syncthreads();

    for (int t = 0; t < T; t++) {
        const int cur = t & 1;
        if (t + 1 < T) fetch(t + 1);

#pragma unroll
        for (int k = 0; k < BK; k++) {
            ulonglong2 a01 = *(const ulonglong2*)&As2[cur][k][ty * 8 + 0];
            ulonglong2 a23 = *(const ulonglong2*)&As2[cur][k][ty * 8 + 2];
            ulonglong2 a45 = *(const ulonglong2*)&As2[cur][k][ty * 8 + 4];
            ulonglong2 a67 = *(const ulonglong2*)&As2[cur][k][ty * 8 + 6];
            ulonglong2 bA = *(const ulonglong2*)&Bs[cur][k][tx * 4];
            ulonglong2 bB = *(const ulonglong2*)&Bs[cur][k][64 + tx * 4];
            fma2(acc[0][0], a01.x, bA.x); fma2(acc[0][1], a01.x, bA.y);
            fma2(acc[0][2], a01.x, bB.x); fma2(acc[0][3], a01.x, bB.y);
            fma2(acc[1][0], a01.y, bA.x); fma2(acc[1][1], a01.y, bA.y);
            fma2(acc[1][2], a01.y, bB.x); fma2(acc[1][3], a01.y, bB.y);
            fma2(acc[2][0], a23.x, bA.x); fma2(acc[2][1], a23.x, bA.y);
            fma2(acc[2][2], a23.x, bB.x); fma2(acc[2][3], a23.x, bB.y);
            fma2(acc[3][0], a23.y, bA.x); fma2(acc[3][1], a23.y, bA.y);
            fma2(acc[3][2], a23.y, bB.x); fma2(acc[3][3], a23.y, bB.y);
            fma2(acc[4][0], a45.x, bA.x); fma2(acc[4][1], a45.x, bA.y);
            fma2(acc[4][2], a45.x, bB.x); fma2(acc[4][3], a45.x, bB.y);
            fma2(acc[5][0], a45.y, bA.x); fma2(acc[5][1], a45.y, bA.y);
            fma2(acc[5][2], a45.y, bB.x); fma2(acc[5][3], a45.y, bB.y);
            fma2(acc[6][0], a67.x, bA.x); fma2(acc[6][1], a67.x, bA.y);
            fma2(acc[6][2], a67.x, bB.x); fma2(acc[6][3], a67.x, bB.y);
            fma2(acc[7][0], a67.y, bA.x); fma2(acc[7][1], a67.y, bA.y);
            fma2(acc[7][2], a67.y, bB.x); fma2(acc[7][3], a67.y, bB.y);
        }

        if (t + 1 < T) store_stage(cur ^ 1);
        __syncthreads();
    }

    // --- fused LSTM epilogue ---
    // cols bn+tx*4 .. +3 = gates (i,f,g,o) of unit u0 = bn/4 + tx;
    // cols bn+64+tx*4    = unit u1 = u0 + 16.
    float4 bia0 = *(const float4*)&bias[bn + tx * 4];
    float4 bia1 = *(const float4*)&bias[bn + 64 + tx * 4];
    const int u0 = (bn >> 2) + tx;

#pragma unroll
    for (int r = 0; r < 8; r++) {
        int row = bm + ty * 8 + r;
        if (row >= M) continue;
#pragma unroll
        for (int jj = 0; jj < 2; jj++) {
            float2 v0 = unpack2(acc[r][2 * jj + 0]);   // (i, f)
            float2 v1 = unpack2(acc[r][2 * jj + 1]);   // (g, o)
            float4 bi = jj ? bia1 : bia0;
            float gi = v0.x + bi.x;
            float gf = v0.y + bi.y;
            float gg = v1.x + bi.z;
            float go = v1.y + bi.w;
            int u = u0 + jj * 16;
            size_t idx = (size_t)row * DIM + u;
            float cp = c[idx];
            float cn = sigf(gf) * cp + sigf(gi) * tanhfast(gg);
            c[idx] = cn;
            hout[idx] = sigf(go) * tanhfast(cn);
        }
    }
}

// ---------------- fused attention: online softmax per segment ----------------
__global__ void attn_kernel(const float* __restrict__ feats,
                            const float* __restrict__ q,
                            float* __restrict__ out) {
    const int s = blockIdx.x;
    const int lo = g_start[s], hi = g_start[s + 1];
    const int w = threadIdx.x >> 5;
    const int lane = threadIdx.x & 31;

    __shared__ float sm_m[8];
    __shared__ float sm_s[8];
    __shared__ float sm_r[8][256];

    const float4* qv = (const float4*)(q + (size_t)s * DIM);
    float4 q0 = qv[lane];
    float4 q1 = qv[lane + 32];

    float m = -INFINITY, ssum = 0.0f;
    float4 r0 = make_float4(0.f, 0.f, 0.f, 0.f);
    float4 r1 = make_float4(0.f, 0.f, 0.f, 0.f);

    for (int n = lo + w; n < hi; n += 8) {
        const float4* f = (const float4*)(feats + (size_t)n * DIM);
        float4 f0 = f[lane];
        float4 f1 = f[lane + 32];
        float d = f0.x * q0.x + f0.y * q0.y + f0.z * q0.z + f0.w * q0.w
                + f1.x * q1.x + f1.y * q1.y + f1.z * q1.z + f1.w * q1.w;
#pragma unroll
        for (int o = 16; o > 0; o >>= 1) d += __shfl_xor_sync(0xffffffffu, d, o);

        float mn = fmaxf(m, d);
        float sc = __expf(m - mn);
        float p  = __expf(d - mn);
        ssum = ssum * sc + p;
        r0.x = r0.x * sc + p * f0.x;  r0.y = r0.y * sc + p * f0.y;
        r0.z = r0.z * sc + p * f0.z;  r0.w = r0.w * sc + p * f0.w;
        r1.x = r1.x * sc + p * f1.x;  r1.y = r1.y * sc + p * f1.y;
        r1.z = r1.z * sc + p * f1.z;  r1.w = r1.w * sc + p * f1.w;
        m = mn;
    }

    if (lane == 0) { sm_m[w] = m; sm_s[w] = ssum; }
    *(float4*)&sm_r[w][4 * lane]       = r0;
    *(float4*)&sm_r[w][128 + 4 * lane] = r1;
    __syncthreads();

    const int t = threadIdx.x;
    float M = -INFINITY;
#pragma unroll
    for (int k = 0; k < 8; k++)
        if (sm_s[k] > 0.0f) M = fmaxf(M, sm_m[k]);
    float S = 0.0f, R = 0.0f;
#pragma unroll
    for (int k = 0; k < 8; k++) {
        if (sm_s[k] > 0.0f) {
            float sc = __expf(sm_m[k] - M);
            S += sm_s[k] * sc;
            R += sm_r[k][t] * sc;
        }
    }
    float rv = (S > 0.0f) ? R / S : 0.0f;
    out[(size_t)s * QSTAR + t]       = q[(size_t)s * DIM + t];
    out[(size_t)s * QSTAR + DIM + t] = rv;
}

// ---------------- host orchestration -----------------------------------------
extern "C" void kernel_launch(void* const* d_in, const int* in_sizes, int n_in,
                              void* d_out, int out_size) {
    const float* feats = (const float*)d_in[0];
    const int* seg = (const int*)d_in[1];
    float* out = (float*)d_out;

    PermArgs pa;
    for (int l = 0; l < 3; l++) {
        pa.w_ih[l] = (const float*)d_in[2 + 4 * l];
        pa.w_hh[l] = (const float*)d_in[3 + 4 * l];
        pa.b_ih[l] = (const float*)d_in[4 + 4 * l];
        pa.b_hh[l] = (const float*)d_in[5 + 4 * l];
        pa.K1[l] = (l == 0) ? QSTAR : DIM;
    }

    float *h, *c, *wp_ih, *wp_hh, *bp;
    cudaGetSymbolAddress((void**)&h, g_h);
    cudaGetSymbolAddress((void**)&c, g_c);
    cudaGetSymbolAddress((void**)&wp_ih, g_wp_ih);
    cudaGetSymbolAddress((void**)&wp_hh, g_wp_hh);
    cudaGetSymbolAddress((void**)&bp, g_bp);

    dim3 pgrid(256, 3);
    prep_kernel<<<pgrid, 256>>>(pa);
    init_kernel<<<1184, 256>>>(seg, out);

    dim3 ggrid((N_SEG + BM - 1) / BM, NGATE / BN);

    for (int it = 0; it < NITER; it++) {
        const float* hin  = h + (size_t)(it & 1) * 3 * SD;
        float*       hout = h + (size_t)((it + 1) & 1) * 3 * SD;
        for (int l = 0; l < 3; l++) {
            const float* A1 = (l == 0) ? out : (hout + (size_t)(l - 1) * SD);
            int K1 = (l == 0) ? QSTAR : DIM;
            gemm_lstm<<<ggrid, 256>>>(A1, K1, wp_ih + (size_t)l * NGATE * 512,
                                      hin + (size_t)l * SD, wp_hh + (size_t)l * NGATE * DIM,
                                      bp + l * NGATE,
                                      c + (size_t)l * SD, hout + (size_t)l * SD, N_SEG);
        }
        attn_kernel<<<N_SEG, 256>>>(feats, hout + (size_t)2 * SD, out);
    }
}

// round 5
// speedup vs baseline: 2.4227x; 1.9081x over previous
#include <cuda_runtime.h>
#include <cuda_bf16.h>
#include <math.h>
#include <stdint.h>

#define N_NODES 500000
#define N_SEG   10000
#define M_PAD   10112            // 79 * 128
#define DIM     256
#define NGATE   1024
#define QSTAR   512
#define NITER   6

typedef __nv_bfloat16 bf16;

// ---------------- scratch (device globals) -----------------------------------
__device__ bf16  g_qstar3[(size_t)M_PAD * 1024];            // row: [hi512 | lo512]
__device__ bf16  g_h3[2 * 3 * (size_t)M_PAD * 512];          // row: [hi256 | lo256]
__device__ float g_c[3 * (size_t)M_PAD * DIM];
__device__ float g_hq[(size_t)M_PAD * DIM];                  // fp32 q for attn
__device__ bf16  g_w3_ih[3][(size_t)NGATE * 1024];           // row: [hi K1 | lo K1]
__device__ bf16  g_w3_hh[3][(size_t)NGATE * 512];            // row: [hi256 | lo256]
__device__ float g_bp[3 * NGATE];
__device__ int   g_start[N_SEG + 1];

// ---------------- helpers ------------------------------------------------------
__device__ __forceinline__ uint32_t smem_u32(const void* p) {
    return (uint32_t)__cvta_generic_to_shared(p);
}
#define SWZ(b) ((b) ^ (((b) >> 3) & 0x70))

__device__ __forceinline__ void cp16(uint32_t dst, const void* src) {
    asm volatile("cp.async.cg.shared.global [%0], [%1], 16;" :: "r"(dst), "l"(src));
}
#define CP_COMMIT() asm volatile("cp.async.commit_group;" ::: "memory")
#define CP_WAIT(n)  asm volatile("cp.async.wait_group %0;" :: "n"(n) : "memory")

__device__ __forceinline__ void ldsm_x4(uint32_t& r0, uint32_t& r1, uint32_t& r2, uint32_t& r3,
                                        uint32_t addr) {
    asm volatile("ldmatrix.sync.aligned.m8n8.x4.shared.b16 {%0,%1,%2,%3}, [%4];"
        : "=r"(r0), "=r"(r1), "=r"(r2), "=r"(r3) : "r"(addr));
}
__device__ __forceinline__ void mma_bf16(float4& d, const uint32_t* a, uint32_t b0, uint32_t b1) {
    asm volatile(
        "mma.sync.aligned.m16n8k16.row.col.f32.bf16.bf16.f32 "
        "{%0,%1,%2,%3}, {%4,%5,%6,%7}, {%8,%9}, {%0,%1,%2,%3};"
        : "+f"(d.x), "+f"(d.y), "+f"(d.z), "+f"(d.w)
        : "r"(a[0]), "r"(a[1]), "r"(a[2]), "r"(a[3]), "r"(b0), "r"(b1));
}

__device__ __forceinline__ float sigf(float x) { return 1.0f / (1.0f + __expf(-x)); }
__device__ __forceinline__ float tanhfast(float x) { return 2.0f / (1.0f + __expf(-2.0f * x)) - 1.0f; }
__device__ __forceinline__ void bsplit(float x, bf16& hi, bf16& lo) {
    hi = __float2bfloat16(x);
    lo = __float2bfloat16(x - __bfloat162float(hi));
}

// ---------------- prep: split + permute weights -------------------------------
struct PermArgs {
    const float* w_ih[3]; const float* w_hh[3];
    const float* b_ih[3]; const float* b_hh[3];
    int K1[3];
};
__global__ void prep_kernel(PermArgs pa) {
    int l = blockIdx.y;
    int K1 = pa.K1[l];
    bf16* wih = g_w3_ih[l];
    bf16* whh = g_w3_hh[l];
    int n_ih = NGATE * K1, n_hh = NGATE * DIM;
    int total = n_ih + n_hh + NGATE;
    for (int i = blockIdx.x * blockDim.x + threadIdx.x; i < total; i += gridDim.x * blockDim.x) {
        if (i < n_ih) {
            int r = i / K1, k = i - r * K1;
            int u = r >> 2, g = r & 3;
            float v = pa.w_ih[l][(size_t)(g * 256 + u) * K1 + k];
            bf16 hi, lo; bsplit(v, hi, lo);
            wih[(size_t)r * (2 * K1) + k] = hi;
            wih[(size_t)r * (2 * K1) + K1 + k] = lo;
        } else if (i < n_ih + n_hh) {
            int j = i - n_ih;
            int r = j / DIM, k = j - r * DIM;
            int u = r >> 2, g = r & 3;
            float v = pa.w_hh[l][(size_t)(g * 256 + u) * DIM + k];
            bf16 hi, lo; bsplit(v, hi, lo);
            whh[(size_t)r * 512 + k] = hi;
            whh[(size_t)r * 512 + 256 + k] = lo;
        } else {
            int r = i - n_ih - n_hh;
            int u = r >> 2, g = r & 3;
            g_bp[l * NGATE + r] = pa.b_ih[l][g * 256 + u] + pa.b_hh[l][g * 256 + u];
        }
    }
}

// ---------------- init ----------------------------------------------------------
__global__ void init_kernel(const int* __restrict__ seg) {
    size_t gid = (size_t)blockIdx.x * blockDim.x + threadIdx.x;
    size_t stride = (size_t)gridDim.x * blockDim.x;
    const size_t nq = (size_t)M_PAD * 1024;
    const size_t nh = (size_t)2 * 3 * M_PAD * 512;
    const size_t nc = (size_t)3 * M_PAD * DIM;
    bf16 z = __float2bfloat16(0.0f);
    for (size_t i = gid; i < nq; i += stride) g_qstar3[i] = z;
    for (size_t i = gid; i < nh; i += stride) g_h3[i] = z;
    for (size_t i = gid; i < nc; i += stride) g_c[i] = 0.0f;
    if (gid <= N_SEG) {
        int s = (int)gid;
        int lo = 0, hi = N_NODES;
        while (lo < hi) { int mid = (lo + hi) >> 1; if (seg[mid] < s) lo = mid + 1; else hi = mid; }
        g_start[s] = lo;
    }
}

// ---------------- HMMA GEMM + fused LSTM cell ----------------------------------
// gates = sum over 6 passes {(Ahi,Whi),(Alo,Whi),(Ahi,Wlo)} x {ih, hh}.
// A1 row: [hi K1 | lo K1], rs = 2*K1; W1 same. A2/W2 rows [hi256|lo256], rs = 512.
// CTA: 128x128 tile, 8 warps (4x2), warp tile 32x64. KC=64 chunks, cp.async pipeline.
#define SM_BUF 16384
#define SMEM_GE 65536

__global__ __launch_bounds__(256)
void gemm_lstm_mma(const bf16* __restrict__ A1, int K1, const bf16* __restrict__ W1,
                   const bf16* __restrict__ A2, const bf16* __restrict__ W2,
                   const float* __restrict__ bias,
                   float* __restrict__ c, bf16* __restrict__ h3out,
                   float* __restrict__ hq, int write_q) {
    extern __shared__ __align__(128) char smem[];
    const uint32_t sbase = smem_u32(smem);
    const int tid = threadIdx.x;
    const int lane = tid & 31;
    const int wid = tid >> 5;
    const int warp_m = wid & 3;       // 4 warps along M (32 rows each)
    const int warp_n = wid >> 2;      // 2 warps along N (64 cols each)
    const int bm = blockIdx.x * 128;
    const int bn = blockIdx.y * 128;

    const int c1 = K1 / 64;           // chunks per ih term
    const int nc = 3 * c1 + 12;       // total chunks

    // per-thread loader mapping: 4 (row, 16B-seg) pairs per operand
    const int l_r  = tid >> 1;                // rows tid/2, +128? no: idx=tid+256q → r=idx>>3
    (void)l_r;

    // chunk loader: resolves pass geometry and issues 8 cp.async
    auto load_chunk = [&](int g, int buf) {
        const bf16* A; const bf16* W; int rs, ao, wo;
        if (g < 3 * c1) {
            int p = g / c1, ci = g - p * c1;
            A = A1; W = W1; rs = 2 * K1;
            ao = ((p == 1) ? K1 : 0) + ci * 64;
            wo = ((p == 2) ? K1 : 0) + ci * 64;
        } else {
            int gg = g - 3 * c1;
            int p = gg >> 2, ci = gg & 3;
            A = A2; W = W2; rs = 512;
            ao = ((p == 1) ? 256 : 0) + ci * 64;
            wo = ((p == 2) ? 256 : 0) + ci * 64;
        }
        uint32_t sA = sbase + buf * 2 * SM_BUF;
        uint32_t sB = sA + SM_BUF;
#pragma unroll
        for (int q = 0; q < 4; q++) {
            int idx = tid + 256 * q;
            int r = idx >> 3, sg = idx & 7;
            uint32_t so = SWZ((uint32_t)(r * 128 + sg * 16));
            cp16(sA + so, A + (size_t)(bm + r) * rs + ao + sg * 8);
            cp16(sB + so, W + (size_t)(bn + r) * rs + wo + sg * 8);
        }
        CP_COMMIT();
    };

    float4 acc[2][8];
#pragma unroll
    for (int i = 0; i < 2; i++)
#pragma unroll
        for (int j = 0; j < 8; j++) acc[i][j] = make_float4(0.f, 0.f, 0.f, 0.f);

    load_chunk(0, 0);
    load_chunk(1, 1);

    // ldmatrix per-lane base: row select (lane&15), k-half select (lane>>4)
    const uint32_t lm_row = (lane & 15);
    const uint32_t lm_koff = (lane >> 4) * 16;

#pragma unroll 1
    for (int g = 0; g < nc; g++) {
        const int buf = g & 1;
        if (g + 1 < nc) { CP_WAIT(1); } else { CP_WAIT(0); }
        __syncthreads();

        const uint32_t sA = sbase + buf * 2 * SM_BUF;
        const uint32_t sB = sA + SM_BUF;

#pragma unroll
        for (int ks = 0; ks < 4; ks++) {
            uint32_t a[2][4];
#pragma unroll
            for (int tm = 0; tm < 2; tm++) {
                uint32_t addr = sA + SWZ((uint32_t)((warp_m * 32 + tm * 16 + lm_row) * 128
                                                    + ks * 32 + lm_koff));
                ldsm_x4(a[tm][0], a[tm][1], a[tm][2], a[tm][3], addr);
            }
            uint32_t b[4][4];
#pragma unroll
            for (int tn2 = 0; tn2 < 4; tn2++) {
                uint32_t addr = sB + SWZ((uint32_t)((warp_n * 64 + tn2 * 16 + lm_row) * 128
                                                    + ks * 32 + lm_koff));
                ldsm_x4(b[tn2][0], b[tn2][1], b[tn2][2], b[tn2][3], addr);
            }
#pragma unroll
            for (int tm = 0; tm < 2; tm++)
#pragma unroll
                for (int tn2 = 0; tn2 < 4; tn2++) {
                    mma_bf16(acc[tm][tn2 * 2 + 0], a[tm], b[tn2][0], b[tn2][2]);
                    mma_bf16(acc[tm][tn2 * 2 + 1], a[tm], b[tn2][1], b[tn2][3]);
                }
        }

        __syncthreads();
        if (g + 2 < nc) load_chunk(g + 2, buf);
    }

    // ---- fused LSTM epilogue ----
    // acc[tm][tn]: rows bm + warp_m*32 + tm*16 + lane/4 (+8), cols bn + warp_n*64 + tn*8 + (lane%4)*2 (+1)
    // even (lane%2==0) threads hold (i,f); odd neighbors hold (g,o) of the same unit.
    const bool even = !(lane & 1);
#pragma unroll
    for (int tm = 0; tm < 2; tm++) {
#pragma unroll
        for (int tn = 0; tn < 8; tn++) {
            float4 d = acc[tm][tn];
            float e0 = __shfl_xor_sync(0xffffffffu, d.x, 1);
            float e1 = __shfl_xor_sync(0xffffffffu, d.y, 1);
            float e2 = __shfl_xor_sync(0xffffffffu, d.z, 1);
            float e3 = __shfl_xor_sync(0xffffffffu, d.w, 1);
            if (even) {
                int col = bn + warp_n * 64 + tn * 8 + (lane & 3) * 2;   // multiple of 4
                int u = col >> 2;
                float4 bi = *(const float4*)&bias[col];
                int rA = bm + warp_m * 32 + tm * 16 + (lane >> 2);
#pragma unroll
                for (int rh = 0; rh < 2; rh++) {
                    int row = rA + rh * 8;
                    float gi = (rh ? d.z : d.x) + bi.x;
                    float gf = (rh ? d.w : d.y) + bi.y;
                    float gg = (rh ? e2 : e0) + bi.z;
                    float go = (rh ? e3 : e1) + bi.w;
                    size_t cidx = (size_t)row * DIM + u;
                    float cn = sigf(gf) * c[cidx] + sigf(gi) * tanhfast(gg);
                    c[cidx] = cn;
                    float hn = sigf(go) * tanhfast(cn);
                    bf16 hh, hl; bsplit(hn, hh, hl);
                    h3out[(size_t)row * 512 + u] = hh;
                    h3out[(size_t)row * 512 + 256 + u] = hl;
                    if (write_q) hq[(size_t)row * DIM + u] = hn;
                }
            }
        }
    }
}

// ---------------- fused attention: online softmax per segment ------------------
__global__ void attn_kernel(const float* __restrict__ feats,
                            const float* __restrict__ q,
                            float* __restrict__ out) {
    const int s = blockIdx.x;
    const int lo = g_start[s], hi = g_start[s + 1];
    const int w = threadIdx.x >> 5;
    const int lane = threadIdx.x & 31;

    __shared__ float sm_m[8];
    __shared__ float sm_s[8];
    __shared__ float sm_r[8][256];

    const float4* qv = (const float4*)(q + (size_t)s * DIM);
    float4 q0 = qv[lane];
    float4 q1 = qv[lane + 32];

    float m = -INFINITY, ssum = 0.0f;
    float4 r0 = make_float4(0.f, 0.f, 0.f, 0.f);
    float4 r1 = make_float4(0.f, 0.f, 0.f, 0.f);

    for (int n = lo + w; n < hi; n += 8) {
        const float4* f = (const float4*)(feats + (size_t)n * DIM);
        float4 f0 = f[lane];
        float4 f1 = f[lane + 32];
        float d = f0.x * q0.x + f0.y * q0.y + f0.z * q0.z + f0.w * q0.w
                + f1.x * q1.x + f1.y * q1.y + f1.z * q1.z + f1.w * q1.w;
#pragma unroll
        for (int o = 16; o > 0; o >>= 1) d += __shfl_xor_sync(0xffffffffu, d, o);

        float mn = fmaxf(m, d);
        float sc = __expf(m - mn);
        float p  = __expf(d - mn);
        ssum = ssum * sc + p;
        r0.x = r0.x * sc + p * f0.x;  r0.y = r0.y * sc + p * f0.y;
        r0.z = r0.z * sc + p * f0.z;  r0.w = r0.w * sc + p * f0.w;
        r1.x = r1.x * sc + p * f1.x;  r1.y = r1.y * sc + p * f1.y;
        r1.z = r1.z * sc + p * f1.z;  r1.w = r1.w * sc + p * f1.w;
        m = mn;
    }

    if (lane == 0) { sm_m[w] = m; sm_s[w] = ssum; }
    *(float4*)&sm_r[w][4 * lane]       = r0;
    *(float4*)&sm_r[w][128 + 4 * lane] = r1;
    __syncthreads();

    const int t = threadIdx.x;
    float M = -INFINITY;
#pragma unroll
    for (int k = 0; k < 8; k++)
        if (sm_s[k] > 0.0f) M = fmaxf(M, sm_m[k]);
    float S = 0.0f, R = 0.0f;
#pragma unroll
    for (int k = 0; k < 8; k++) {
        if (sm_s[k] > 0.0f) {
            float sc = __expf(sm_m[k] - M);
            S += sm_s[k] * sc;
            R += sm_r[k][t] * sc;
        }
    }
    float rv = (S > 0.0f) ? R / S : 0.0f;
    float qv_ = q[(size_t)s * DIM + t];
    out[(size_t)s * QSTAR + t]       = qv_;
    out[(size_t)s * QSTAR + DIM + t] = rv;

    bf16 qh, ql, rh, rl;
    bsplit(qv_, qh, ql); bsplit(rv, rh, rl);
    bf16* qs = g_qstar3 + (size_t)s * 1024;
    qs[t]             = qh;
    qs[256 + t]       = rh;
    qs[512 + t]       = ql;
    qs[512 + 256 + t] = rl;
}

// ---------------- host orchestration -------------------------------------------
extern "C" void kernel_launch(void* const* d_in, const int* in_sizes, int n_in,
                              void* d_out, int out_size) {
    const float* feats = (const float*)d_in[0];
    const int* seg = (const int*)d_in[1];
    float* out = (float*)d_out;

    PermArgs pa;
    for (int l = 0; l < 3; l++) {
        pa.w_ih[l] = (const float*)d_in[2 + 4 * l];
        pa.w_hh[l] = (const float*)d_in[3 + 4 * l];
        pa.b_ih[l] = (const float*)d_in[4 + 4 * l];
        pa.b_hh[l] = (const float*)d_in[5 + 4 * l];
        pa.K1[l] = (l == 0) ? QSTAR : DIM;
    }

    bf16 *qs3, *h3; float *c, *hq, *bp; bf16 *wih[3], *whh[3];
    cudaGetSymbolAddress((void**)&qs3, g_qstar3);
    cudaGetSymbolAddress((void**)&h3, g_h3);
    cudaGetSymbolAddress((void**)&c, g_c);
    cudaGetSymbolAddress((void**)&hq, g_hq);
    cudaGetSymbolAddress((void**)&bp, g_bp);
    {
        bf16* base_ih; bf16* base_hh;
        cudaGetSymbolAddress((void**)&base_ih, g_w3_ih);
        cudaGetSymbolAddress((void**)&base_hh, g_w3_hh);
        for (int l = 0; l < 3; l++) {
            wih[l] = base_ih + (size_t)l * NGATE * 1024;
            whh[l] = base_hh + (size_t)l * NGATE * 512;
        }
    }

    cudaFuncSetAttribute(gemm_lstm_mma, cudaFuncAttributeMaxDynamicSharedMemorySize, SMEM_GE);

    dim3 pgrid(256, 3);
    prep_kernel<<<pgrid, 256>>>(pa);
    init_kernel<<<1184, 256>>>(seg);

    const size_t SD3 = (size_t)M_PAD * 512;
    dim3 ggrid(M_PAD / 128, NGATE / 128);

    for (int it = 0; it < NITER; it++) {
        bf16* h3in  = h3 + (size_t)(it & 1) * 3 * SD3;
        bf16* h3out = h3 + (size_t)((it + 1) & 1) * 3 * SD3;
        for (int l = 0; l < 3; l++) {
            const bf16* A1 = (l == 0) ? qs3 : (h3out + (size_t)(l - 1) * SD3);
            int K1 = (l == 0) ? QSTAR : DIM;
            gemm_lstm_mma<<<ggrid, 256, SMEM_GE>>>(
                A1, K1, wih[l],
                h3in + (size_t)l * SD3, whh[l],
                bp + l * NGATE,
                c + (size_t)l * M_PAD * DIM,
                h3out + (size_t)l * SD3,
                hq, (l == 2) ? 1 : 0);
        }
        attn_kernel<<<N_SEG, 256>>>(feats, hq, out);
    }
}

// round 6
// speedup vs baseline: 2.5318x; 1.0450x over previous
#include <cuda_runtime.h>
#include <cuda_bf16.h>
#include <math.h>
#include <stdint.h>

#define N_NODES 500000
#define N_SEG   10000
#define M_PAD   10112            // 79 * 128
#define DIM     256
#define NGATE   1024
#define QSTAR   512
#define NITER   6

typedef __nv_bfloat16 bf16;

// ---------------- scratch (device globals) -----------------------------------
__device__ bf16  g_qstar3[(size_t)M_PAD * 1024];            // row: [hi512 | lo512]
__device__ bf16  g_h3[2 * 3 * (size_t)M_PAD * 512];          // row: [hi256 | lo256]
__device__ float g_c[3 * (size_t)M_PAD * DIM];
__device__ float g_hq[(size_t)M_PAD * DIM];                  // fp32 q for attn
__device__ bf16  g_w3_ih[3][(size_t)NGATE * 1024];           // row: [hi K1 | lo K1]
__device__ bf16  g_w3_hh[3][(size_t)NGATE * 512];            // row: [hi256 | lo256]
__device__ float g_bp[3 * NGATE];
__device__ int   g_start[N_SEG + 1];

// ---------------- helpers ------------------------------------------------------
__device__ __forceinline__ uint32_t smem_u32(const void* p) {
    return (uint32_t)__cvta_generic_to_shared(p);
}
#define SWZ(b) ((b) ^ (((b) >> 3) & 0x70))

__device__ __forceinline__ void cp16(uint32_t dst, const void* src) {
    asm volatile("cp.async.cg.shared.global [%0], [%1], 16;" :: "r"(dst), "l"(src));
}
#define CP_COMMIT() asm volatile("cp.async.commit_group;" ::: "memory")
#define CP_WAIT(n)  asm volatile("cp.async.wait_group %0;" :: "n"(n) : "memory")

__device__ __forceinline__ void ldsm_x4(uint32_t& r0, uint32_t& r1, uint32_t& r2, uint32_t& r3,
                                        uint32_t addr) {
    asm volatile("ldmatrix.sync.aligned.m8n8.x4.shared.b16 {%0,%1,%2,%3}, [%4];"
        : "=r"(r0), "=r"(r1), "=r"(r2), "=r"(r3) : "r"(addr));
}
__device__ __forceinline__ void mma_bf16(float4& d, const uint32_t* a, uint32_t b0, uint32_t b1) {
    asm volatile(
        "mma.sync.aligned.m16n8k16.row.col.f32.bf16.bf16.f32 "
        "{%0,%1,%2,%3}, {%4,%5,%6,%7}, {%8,%9}, {%0,%1,%2,%3};"
        : "+f"(d.x), "+f"(d.y), "+f"(d.z), "+f"(d.w)
        : "r"(a[0]), "r"(a[1]), "r"(a[2]), "r"(a[3]), "r"(b0), "r"(b1));
}

__device__ __forceinline__ float sigf(float x) { return 1.0f / (1.0f + __expf(-x)); }
__device__ __forceinline__ float tanhfast(float x) { return 2.0f / (1.0f + __expf(-2.0f * x)) - 1.0f; }
__device__ __forceinline__ void bsplit(float x, bf16& hi, bf16& lo) {
    hi = __float2bfloat16(x);
    lo = __float2bfloat16(x - __bfloat162float(hi));
}

// ---------------- prep: split + permute weights -------------------------------
struct PermArgs {
    const float* w_ih[3]; const float* w_hh[3];
    const float* b_ih[3]; const float* b_hh[3];
    int K1[3];
};
__global__ void prep_kernel(PermArgs pa) {
    int l = blockIdx.y;
    int K1 = pa.K1[l];
    bf16* wih = g_w3_ih[l];
    bf16* whh = g_w3_hh[l];
    int n_ih = NGATE * K1, n_hh = NGATE * DIM;
    int total = n_ih + n_hh + NGATE;
    for (int i = blockIdx.x * blockDim.x + threadIdx.x; i < total; i += gridDim.x * blockDim.x) {
        if (i < n_ih) {
            int r = i / K1, k = i - r * K1;
            int u = r >> 2, g = r & 3;
            float v = pa.w_ih[l][(size_t)(g * 256 + u) * K1 + k];
            bf16 hi, lo; bsplit(v, hi, lo);
            wih[(size_t)r * (2 * K1) + k] = hi;
            wih[(size_t)r * (2 * K1) + K1 + k] = lo;
        } else if (i < n_ih + n_hh) {
            int j = i - n_ih;
            int r = j / DIM, k = j - r * DIM;
            int u = r >> 2, g = r & 3;
            float v = pa.w_hh[l][(size_t)(g * 256 + u) * DIM + k];
            bf16 hi, lo; bsplit(v, hi, lo);
            whh[(size_t)r * 512 + k] = hi;
            whh[(size_t)r * 512 + 256 + k] = lo;
        } else {
            int r = i - n_ih - n_hh;
            int u = r >> 2, g = r & 3;
            g_bp[l * NGATE + r] = pa.b_ih[l][g * 256 + u] + pa.b_hh[l][g * 256 + u];
        }
    }
}

// ---------------- init ----------------------------------------------------------
__global__ void init_kernel(const int* __restrict__ seg) {
    size_t gid = (size_t)blockIdx.x * blockDim.x + threadIdx.x;
    size_t stride = (size_t)gridDim.x * blockDim.x;
    const size_t nq = (size_t)M_PAD * 1024;
    const size_t nh = (size_t)2 * 3 * M_PAD * 512;
    const size_t nc = (size_t)3 * M_PAD * DIM;
    bf16 z = __float2bfloat16(0.0f);
    for (size_t i = gid; i < nq; i += stride) g_qstar3[i] = z;
    for (size_t i = gid; i < nh; i += stride) g_h3[i] = z;
    for (size_t i = gid; i < nc; i += stride) g_c[i] = 0.0f;
    if (gid <= N_SEG) {
        int s = (int)gid;
        int lo = 0, hi = N_NODES;
        while (lo < hi) { int mid = (lo + hi) >> 1; if (seg[mid] < s) lo = mid + 1; else hi = mid; }
        g_start[s] = lo;
    }
}

// ---------------- HMMA GEMM + fused LSTM cell ----------------------------------
// gates = sum over 6 passes {(Ahi,Whi),(Alo,Whi),(Ahi,Wlo)} x {ih, hh}.
// Templated on K1 so chunk geometry is compile-time (no runtime div).
#define SM_BUF 16384
#define SMEM_GE 65536

template<int K1>
__global__ __launch_bounds__(256, 2)
void gemm_lstm_mma(const bf16* __restrict__ A1, const bf16* __restrict__ W1,
                   const bf16* __restrict__ A2, const bf16* __restrict__ W2,
                   const float* __restrict__ bias,
                   float* __restrict__ c, bf16* __restrict__ h3out,
                   float* __restrict__ hq, int write_q) {
    extern __shared__ __align__(128) char smem[];
    const uint32_t sbase = smem_u32(smem);
    const int tid = threadIdx.x;
    const int lane = tid & 31;
    const int wid = tid >> 5;
    const int warp_m = wid & 3;
    const int warp_n = wid >> 2;
    const int bm = blockIdx.x * 128;
    const int bn = blockIdx.y * 128;

    constexpr int C1 = K1 / 64;          // chunks per ih term (8 or 4)
    constexpr int NC = 3 * C1 + 12;      // total chunks

    // loader: idx = tid + 256q -> row r = idx>>3, 16B segment sg = idx&7
    // smem offset so = r*128 + ((sg*16) ^ ((r&7)<<4))   (row-local swizzle)
    auto load_chunk = [&](int g, int buf) {
        const bf16* A; const bf16* W; int rs, ao, wo;
        if (g < 3 * C1) {
            int p = g / C1, ci = g - p * C1;          // constexpr divisor -> shifts
            A = A1; W = W1; rs = 2 * K1;
            ao = ((p == 1) ? K1 : 0) + ci * 64;
            wo = ((p == 2) ? K1 : 0) + ci * 64;
        } else {
            int gg = g - 3 * C1;
            int p = gg >> 2, ci = gg & 3;
            A = A2; W = W2; rs = 512;
            ao = ((p == 1) ? 256 : 0) + ci * 64;
            wo = ((p == 2) ? 256 : 0) + ci * 64;
        }
        uint32_t sA = sbase + buf * 2 * SM_BUF;
        uint32_t sB = sA + SM_BUF;
#pragma unroll
        for (int q = 0; q < 4; q++) {
            int idx = tid + 256 * q;
            int r = idx >> 3, sg = idx & 7;
            uint32_t so = (uint32_t)(r * 128 + ((sg * 16) ^ ((r & 7) << 4)));
            cp16(sA + so, A + (size_t)(bm + r) * rs + ao + sg * 8);
            cp16(sB + so, W + (size_t)(bn + r) * rs + wo + sg * 8);
        }
        CP_COMMIT();
    };

    float4 acc[2][8];
#pragma unroll
    for (int i = 0; i < 2; i++)
#pragma unroll
        for (int j = 0; j < 8; j++) acc[i][j] = make_float4(0.f, 0.f, 0.f, 0.f);

    load_chunk(0, 0);
    load_chunk(1, 1);

    // hoisted ldmatrix addressing: addr = base + bufoff + ((ks*32) ^ xc)
    const int koff = (lane >> 4) * 16;
    uint32_t a_base[2], a_xc[2], b_base[4], b_xc[4];
#pragma unroll
    for (int tm = 0; tm < 2; tm++) {
        int row = warp_m * 32 + tm * 16 + (lane & 15);
        a_base[tm] = sbase + row * 128;
        a_xc[tm] = (uint32_t)(koff ^ ((row & 7) << 4));
    }
#pragma unroll
    for (int tn2 = 0; tn2 < 4; tn2++) {
        int row = warp_n * 64 + tn2 * 16 + (lane & 15);
        b_base[tn2] = sbase + SM_BUF + row * 128;
        b_xc[tn2] = (uint32_t)(koff ^ ((row & 7) << 4));
    }

#pragma unroll 1
    for (int g = 0; g < NC; g++) {
        const uint32_t bufoff = (g & 1) * (2 * SM_BUF);
        if (g + 1 < NC) { CP_WAIT(1); } else { CP_WAIT(0); }
        __syncthreads();

#pragma unroll
        for (int ks = 0; ks < 4; ks++) {
            uint32_t a[2][4];
#pragma unroll
            for (int tm = 0; tm < 2; tm++)
                ldsm_x4(a[tm][0], a[tm][1], a[tm][2], a[tm][3],
                        a_base[tm] + bufoff + ((uint32_t)(ks * 32) ^ a_xc[tm]));
            uint32_t b[4][4];
#pragma unroll
            for (int tn2 = 0; tn2 < 4; tn2++)
                ldsm_x4(b[tn2][0], b[tn2][1], b[tn2][2], b[tn2][3],
                        b_base[tn2] + bufoff + ((uint32_t)(ks * 32) ^ b_xc[tn2]));
#pragma unroll
            for (int tm = 0; tm < 2; tm++)
#pragma unroll
                for (int tn2 = 0; tn2 < 4; tn2++) {
                    mma_bf16(acc[tm][tn2 * 2 + 0], a[tm], b[tn2][0], b[tn2][2]);
                    mma_bf16(acc[tm][tn2 * 2 + 1], a[tm], b[tn2][1], b[tn2][3]);
                }
        }

        __syncthreads();
        if (g + 2 < NC) load_chunk(g + 2, g & 1);
    }

    // ---- fused LSTM epilogue (unchanged semantics from R5) ----
    const bool even = !(lane & 1);
#pragma unroll
    for (int tm = 0; tm < 2; tm++) {
#pragma unroll
        for (int tn = 0; tn < 8; tn++) {
            float4 d = acc[tm][tn];
            float e0 = __shfl_xor_sync(0xffffffffu, d.x, 1);
            float e1 = __shfl_xor_sync(0xffffffffu, d.y, 1);
            float e2 = __shfl_xor_sync(0xffffffffu, d.z, 1);
            float e3 = __shfl_xor_sync(0xffffffffu, d.w, 1);
            if (even) {
                int col = bn + warp_n * 64 + tn * 8 + (lane & 3) * 2;
                int u = col >> 2;
                float4 bi = *(const float4*)&bias[col];
                int rA = bm + warp_m * 32 + tm * 16 + (lane >> 2);
#pragma unroll
                for (int rh = 0; rh < 2; rh++) {
                    int row = rA + rh * 8;
                    float gi = (rh ? d.z : d.x) + bi.x;
                    float gf = (rh ? d.w : d.y) + bi.y;
                    float gg = (rh ? e2 : e0) + bi.z;
                    float go = (rh ? e3 : e1) + bi.w;
                    size_t cidx = (size_t)row * DIM + u;
                    float cn = sigf(gf) * c[cidx] + sigf(gi) * tanhfast(gg);
                    c[cidx] = cn;
                    float hn = sigf(go) * tanhfast(cn);
                    bf16 hh, hl; bsplit(hn, hh, hl);
                    h3out[(size_t)row * 512 + u] = hh;
                    h3out[(size_t)row * 512 + 256 + u] = hl;
                    if (write_q) hq[(size_t)row * DIM + u] = hn;
                }
            }
        }
    }
}

// ---------------- fused attention: online softmax per segment ------------------
__global__ void attn_kernel(const float* __restrict__ feats,
                            const float* __restrict__ q,
                            float* __restrict__ out) {
    const int s = blockIdx.x;
    const int lo = g_start[s], hi = g_start[s + 1];
    const int w = threadIdx.x >> 5;
    const int lane = threadIdx.x & 31;

    __shared__ float sm_m[8];
    __shared__ float sm_s[8];
    __shared__ float sm_r[8][256];

    const float4* qv = (const float4*)(q + (size_t)s * DIM);
    float4 q0 = qv[lane];
    float4 q1 = qv[lane + 32];

    float m = -INFINITY, ssum = 0.0f;
    float4 r0 = make_float4(0.f, 0.f, 0.f, 0.f);
    float4 r1 = make_float4(0.f, 0.f, 0.f, 0.f);

    for (int n = lo + w; n < hi; n += 8) {
        const float4* f = (const float4*)(feats + (size_t)n * DIM);
        float4 f0 = f[lane];
        float4 f1 = f[lane + 32];
        float d = f0.x * q0.x + f0.y * q0.y + f0.z * q0.z + f0.w * q0.w
                + f1.x * q1.x + f1.y * q1.y + f1.z * q1.z + f1.w * q1.w;
#pragma unroll
        for (int o = 16; o > 0; o >>= 1) d += __shfl_xor_sync(0xffffffffu, d, o);

        float mn = fmaxf(m, d);
        float sc = __expf(m - mn);
        float p  = __expf(d - mn);
        ssum = ssum * sc + p;
        r0.x = r0.x * sc + p * f0.x;  r0.y = r0.y * sc + p * f0.y;
        r0.z = r0.z * sc + p * f0.z;  r0.w = r0.w * sc + p * f0.w;
        r1.x = r1.x * sc + p * f1.x;  r1.y = r1.y * sc + p * f1.y;
        r1.z = r1.z * sc + p * f1.z;  r1.w = r1.w * sc + p * f1.w;
        m = mn;
    }

    if (lane == 0) { sm_m[w] = m; sm_s[w] = ssum; }
    *(float4*)&sm_r[w][4 * lane]       = r0;
    *(float4*)&sm_r[w][128 + 4 * lane] = r1;
    __syncthreads();

    const int t = threadIdx.x;
    float M = -INFINITY;
#pragma unroll
    for (int k = 0; k < 8; k++)
        if (sm_s[k] > 0.0f) M = fmaxf(M, sm_m[k]);
    float S = 0.0f, R = 0.0f;
#pragma unroll
    for (int k = 0; k < 8; k++) {
        if (sm_s[k] > 0.0f) {
            float sc = __expf(sm_m[k] - M);
            S += sm_s[k] * sc;
            R += sm_r[k][t] * sc;
        }
    }
    float rv = (S > 0.0f) ? R / S : 0.0f;
    float qv_ = q[(size_t)s * DIM + t];
    out[(size_t)s * QSTAR + t]       = qv_;
    out[(size_t)s * QSTAR + DIM + t] = rv;

    bf16 qh, ql, rh, rl;
    bsplit(qv_, qh, ql); bsplit(rv, rh, rl);
    bf16* qs = g_qstar3 + (size_t)s * 1024;
    qs[t]             = qh;
    qs[256 + t]       = rh;
    qs[512 + t]       = ql;
    qs[512 + 256 + t] = rl;
}

// ---------------- host orchestration -------------------------------------------
extern "C" void kernel_launch(void* const* d_in, const int* in_sizes, int n_in,
                              void* d_out, int out_size) {
    const float* feats = (const float*)d_in[0];
    const int* seg = (const int*)d_in[1];
    float* out = (float*)d_out;

    PermArgs pa;
    for (int l = 0; l < 3; l++) {
        pa.w_ih[l] = (const float*)d_in[2 + 4 * l];
        pa.w_hh[l] = (const float*)d_in[3 + 4 * l];
        pa.b_ih[l] = (const float*)d_in[4 + 4 * l];
        pa.b_hh[l] = (const float*)d_in[5 + 4 * l];
        pa.K1[l] = (l == 0) ? QSTAR : DIM;
    }

    bf16 *qs3, *h3; float *c, *hq, *bp; bf16 *wih[3], *whh[3];
    cudaGetSymbolAddress((void**)&qs3, g_qstar3);
    cudaGetSymbolAddress((void**)&h3, g_h3);
    cudaGetSymbolAddress((void**)&c, g_c);
    cudaGetSymbolAddress((void**)&hq, g_hq);
    cudaGetSymbolAddress((void**)&bp, g_bp);
    {
        bf16* base_ih; bf16* base_hh;
        cudaGetSymbolAddress((void**)&base_ih, g_w3_ih);
        cudaGetSymbolAddress((void**)&base_hh, g_w3_hh);
        for (int l = 0; l < 3; l++) {
            wih[l] = base_ih + (size_t)l * NGATE * 1024;
            whh[l] = base_hh + (size_t)l * NGATE * 512;
        }
    }

    cudaFuncSetAttribute(gemm_lstm_mma<512>, cudaFuncAttributeMaxDynamicSharedMemorySize, SMEM_GE);
    cudaFuncSetAttribute(gemm_lstm_mma<256>, cudaFuncAttributeMaxDynamicSharedMemorySize, SMEM_GE);

    dim3 pgrid(256, 3);
    prep_kernel<<<pgrid, 256>>>(pa);
    init_kernel<<<1184, 256>>>(seg);

    const size_t SD3 = (size_t)M_PAD * 512;
    dim3 ggrid(M_PAD / 128, NGATE / 128);

    for (int it = 0; it < NITER; it++) {
        bf16* h3in  = h3 + (size_t)(it & 1) * 3 * SD3;
        bf16* h3out = h3 + (size_t)((it + 1) & 1) * 3 * SD3;
        for (int l = 0; l < 3; l++) {
            const bf16* A1 = (l == 0) ? qs3 : (h3out + (size_t)(l - 1) * SD3);
            if (l == 0) {
                gemm_lstm_mma<512><<<ggrid, 256, SMEM_GE>>>(
                    A1, wih[l], h3in + (size_t)l * SD3, whh[l],
                    bp + l * NGATE, c + (size_t)l * M_PAD * DIM,
                    h3out + (size_t)l * SD3, hq, 0);
            } else {
                gemm_lstm_mma<256><<<ggrid, 256, SMEM_GE>>>(
                    A1, wih[l], h3in + (size_t)l * SD3, whh[l],
                    bp + l * NGATE, c + (size_t)l * M_PAD * DIM,
                    h3out + (size_t)l * SD3, hq, (l == 2) ? 1 : 0);
            }
        }
        attn_kernel<<<N_SEG, 256>>>(feats, hq, out);
    }
}